// round 14
// baseline (speedup 1.0000x reference)
#include <cuda_runtime.h>
#include <cuda_fp16.h>
#include <cstdint>

// ---------------------------------------------------------------------------
// Problem shape / tiling
// ---------------------------------------------------------------------------
#define BSZ    16384
#define DDIM   128
#define TILE_M 512               // rows per row-tile
#define TILE_N 128               // cols per tile step
#define NRT    (BSZ / TILE_M)    // 32 row tiles
#define NCHUNK 32                // items per row tile (4 col tiles each)
#define NITEMS (NRT * NCHUNK)    // 1024 work items
#define GRID_PERS 148
#define NWARPS_G (GRID_PERS * 16)
#define ROWS_PER_CTA 111
#define NEGINF_LO 0x0000FC00u
#define NEGINF_HI 0xFC000000u

// Scratch (device globals; allocation-free rule)
__device__ __align__(128) __half g_Qh[BSZ * DDIM];   // 4 MB
__device__ __align__(128) __half g_Dh[BSZ * DDIM];   // 4 MB
__device__ float    g_pos[BSZ];
__device__ float    g_term1[BSZ];
__device__ unsigned g_rowmax_enc[BSZ];
__device__ float    g_part[160];
__device__ int      g_prep;
__device__ int      g_done;
__device__ int      g_done2;

// ---------------------------------------------------------------------------
// helpers
// ---------------------------------------------------------------------------
__device__ __forceinline__ uint32_t smem_to_u32(const void* p) {
    uint32_t a;
    asm("{ .reg .u64 t; cvta.to.shared.u64 t, %1; cvt.u32.u64 %0, t; }" : "=r"(a) : "l"(p));
    return a;
}
__device__ __forceinline__ void cpasync16(uint32_t s, const void* g) {
    asm volatile("cp.async.cg.shared.global [%0], [%1], 16;" :: "r"(s), "l"(g));
}
#define CP_COMMIT() asm volatile("cp.async.commit_group;" ::: "memory")
#define CP_WAIT0()  asm volatile("cp.async.wait_group 0;" ::: "memory")
#define CP_WAIT1()  asm volatile("cp.async.wait_group 1;" ::: "memory")

__device__ __forceinline__ void ldsm4(uint32_t* r, uint32_t addr) {
    asm volatile("ldmatrix.sync.aligned.m8n8.x4.shared.b16 {%0,%1,%2,%3}, [%4];"
                 : "=r"(r[0]), "=r"(r[1]), "=r"(r[2]), "=r"(r[3]) : "r"(addr));
}
__device__ __forceinline__ void mma16816h(uint32_t* c, const uint32_t* a, uint32_t b0, uint32_t b1) {
    asm volatile("mma.sync.aligned.m16n8k16.row.col.f16.f16.f16.f16 "
                 "{%0,%1}, {%2,%3,%4,%5}, {%6,%7}, {%0,%1};"
                 : "+r"(c[0]), "+r"(c[1])
                 : "r"(a[0]), "r"(a[1]), "r"(a[2]), "r"(a[3]), "r"(b0), "r"(b1));
}
__device__ __forceinline__ uint32_t hmax2(uint32_t a, uint32_t b) {
    uint32_t d;
    asm("max.f16x2 %0, %1, %2;" : "=r"(d) : "r"(a), "r"(b));
    return d;
}
__device__ __forceinline__ float softplusf(float x) {
    return x > 20.0f ? x : log1pf(__expf(x));
}
__device__ __forceinline__ unsigned enc_f(float x) {
    unsigned u = __float_as_uint(x);
    return (u & 0x80000000u) ? ~u : (u | 0x80000000u);
}
__device__ __forceinline__ float dec_f(unsigned e) {
    unsigned u = (e & 0x80000000u) ? (e & 0x7FFFFFFFu) : ~e;
    return __uint_as_float(u);
}
__device__ __forceinline__ void spin_until(int* ctr, int target) {
    while (atomicAdd(ctr, 0) < target) { __nanosleep(64); }
}

// one row's prep work given preloaded vectors
__device__ __forceinline__ void prep_row(int row, int lane,
                                         const float4& qv, const float4& dv, const float4& nv) {
    __half2* qdst = (__half2*)(g_Qh + (size_t)row * DDIM + lane * 4);
    qdst[0] = __floats2half2_rn(qv.x, qv.y);
    qdst[1] = __floats2half2_rn(qv.z, qv.w);
    __half2* ddst = (__half2*)(g_Dh + (size_t)row * DDIM + lane * 4);
    ddst[0] = __floats2half2_rn(dv.x, dv.y);
    ddst[1] = __floats2half2_rn(dv.z, dv.w);

    float pos = qv.x * dv.x + qv.y * dv.y + qv.z * dv.z + qv.w * dv.w;
    float neg = qv.x * nv.x + qv.y * nv.y + qv.z * nv.z + qv.w * nv.w;
    #pragma unroll
    for (int off = 16; off > 0; off >>= 1) {
        pos += __shfl_xor_sync(0xFFFFFFFFu, pos, off);
        neg += __shfl_xor_sync(0xFFFFFFFFu, neg, off);
    }
    if (lane == 0) {
        g_pos[row]   = pos;
        g_term1[row] = softplusf(neg - pos);
        g_rowmax_enc[row] = 0u;
    }
}

// ---------------------------------------------------------------------------
// smem: A (512 rows x 256B = 128KB) + B ring x3 (128 rows x 256B each)
// ---------------------------------------------------------------------------
#define SMEM_A     0
#define SMEM_BR    131072          // + slot * 32768, 3 slots
#define SMEM_TOTAL 229376

// swizzle: 16B chunk c of row r lives at chunk (c ^ (r & 7))
__device__ __forceinline__ void load_tileA_sw(uint32_t dst, const __half* src,
                                              int rowBase, int tid) {
    const char* s = (const char*)(src + (size_t)rowBase * DDIM);
    #pragma unroll
    for (int i = 0; i < 16; ++i) {
        int e = tid + 512 * i;         // 8192 chunks (512 rows x 16)
        int r = e >> 4;
        int c = e & 15;
        cpasync16(dst + r * 256 + ((c ^ (r & 7)) << 4), s + (size_t)r * 256 + c * 16);
    }
}
__device__ __forceinline__ void load_tileB_sw(uint32_t dst, const __half* src,
                                              int rowBase, int tid) {
    const char* s = (const char*)(src + (size_t)rowBase * DDIM);
    #pragma unroll
    for (int i = 0; i < 4; ++i) {
        int e = tid + 512 * i;         // 2048 chunks (128 rows x 16)
        int r = e >> 4;
        int c = e & 15;
        cpasync16(dst + r * 256 + ((c ^ (r & 7)) << 4), s + (size_t)r * 256 + c * 16);
    }
}

// ---------------------------------------------------------------------------
// ONE persistent kernel; static contiguous item partition, A reused per segment
// ---------------------------------------------------------------------------
__global__ void __launch_bounds__(512, 1)
mega_kernel(const float* __restrict__ q, const float* __restrict__ d,
            const float* __restrict__ nd, float* __restrict__ out) {
    extern __shared__ __align__(1024) char smem[];
    __shared__ int s_flag;
    const uint32_t sb = smem_to_u32(smem);
    const int tid  = threadIdx.x;
    const int lane = tid & 31;
    const int wid  = tid >> 5;
    const int wm   = wid >> 1;        // 0..7  (M position, 64 rows each)
    const int wn   = wid & 1;         // 0..1  (N position, 64 cols each)

    // ---------------- Phase 0: prep (2-row unroll for MLP) ------------------
    {
        int gw = blockIdx.x * 16 + wid;
        int row = gw;
        for (; row + NWARPS_G < BSZ; row += 2 * NWARPS_G) {
            const int row2 = row + NWARPS_G;
            // issue all 6 loads before any dependent work
            const float4 qv1 = *(const float4*)(q  + (size_t)row  * DDIM + lane * 4);
            const float4 dv1 = *(const float4*)(d  + (size_t)row  * DDIM + lane * 4);
            const float4 nv1 = *(const float4*)(nd + (size_t)row  * DDIM + lane * 4);
            const float4 qv2 = *(const float4*)(q  + (size_t)row2 * DDIM + lane * 4);
            const float4 dv2 = *(const float4*)(d  + (size_t)row2 * DDIM + lane * 4);
            const float4 nv2 = *(const float4*)(nd + (size_t)row2 * DDIM + lane * 4);
            prep_row(row,  lane, qv1, dv1, nv1);
            prep_row(row2, lane, qv2, dv2, nv2);
        }
        if (row < BSZ) {
            const float4 qv = *(const float4*)(q  + (size_t)row * DDIM + lane * 4);
            const float4 dv = *(const float4*)(d  + (size_t)row * DDIM + lane * 4);
            const float4 nv = *(const float4*)(nd + (size_t)row * DDIM + lane * 4);
            prep_row(row, lane, qv, dv, nv);
        }
    }
    __threadfence();
    __syncthreads();
    if (tid == 0) { atomicAdd(&g_prep, 1); spin_until(&g_prep, GRID_PERS); }
    __syncthreads();

    // ---------------- Phase 1: static-partition max-GEMM --------------------
    const int xr  = lane & 7;
    const int hcA = (lane >> 4) & 1;
    const int hcB = (lane >> 3) & 1;
    const uint32_t aRow    = (uint32_t)((wm * 64 + (lane & 15)) * 256);
    const uint32_t bRowOff = (uint32_t)((wn * 64 + ((lane >> 4) << 3) + (lane & 7)) * 256);

    const int iStart = (blockIdx.x * NITEMS) / GRID_PERS;
    const int iEnd   = ((blockIdx.x + 1) * NITEMS) / GRID_PERS;

    int i0 = iStart;
    while (i0 < iEnd) {
        const int rt = i0 >> 5;                         // row tile of this segment
        const int i1 = min(iEnd, (rt + 1) << 5);        // segment end (same rt)
        const int rowBase = rt * TILE_M;
        const int ct0 = (i0 & 31) * 4;                  // first global col tile
        const int ctN = (i1 - i0) * 4;                  // number of col tiles

        __syncthreads();   // all warps past previous segment's smem reads

        // prologue: group0 = A + B(ct0); group1 = B(ct0+1) (maybe empty)
        load_tileA_sw(sb + SMEM_A, g_Qh, rowBase, tid);
        load_tileB_sw(sb + SMEM_BR, g_Dh, (ct0 + 0) * TILE_N, tid);
        CP_COMMIT();
        if (ctN > 1)
            load_tileB_sw(sb + SMEM_BR + 32768, g_Dh, (ct0 + 1) * TILE_N, tid);
        CP_COMMIT();

        uint32_t rmax2[4][2];
        #pragma unroll
        for (int mi = 0; mi < 4; ++mi) { rmax2[mi][0] = 0xFC00FC00u; rmax2[mi][1] = 0xFC00FC00u; }

        for (int k = 0; k < ctN; ++k) {
            CP_WAIT1();            // group k complete
            __syncthreads();
            // prefetch B(ct0+k+2); ALWAYS commit to keep group count uniform
            if (k + 2 < ctN)
                load_tileB_sw(sb + SMEM_BR + (uint32_t)(((k + 2) % 3) * 32768),
                              g_Dh, (ct0 + k + 2) * TILE_N, tid);
            CP_COMMIT();

            const uint32_t aBufBase = sb + SMEM_A + aRow;
            const uint32_t bBufBase = sb + SMEM_BR + (uint32_t)((k % 3) * 32768) + bRowOff;

            uint32_t acc[4][8][2];
            #pragma unroll
            for (int mi = 0; mi < 4; ++mi)
                #pragma unroll
                for (int ni = 0; ni < 8; ++ni) { acc[mi][ni][0] = 0u; acc[mi][ni][1] = 0u; }

            #pragma unroll
            for (int ks = 0; ks < 8; ++ks) {
                const uint32_t aCh = (uint32_t)(((ks * 2 + hcA) ^ xr) << 4);
                const uint32_t bCh = (uint32_t)(((ks * 2 + hcB) ^ xr) << 4);
                uint32_t a[4][4];
                #pragma unroll
                for (int mi = 0; mi < 4; ++mi)
                    ldsm4(a[mi], aBufBase + (uint32_t)(mi * 4096) + aCh);
                uint32_t b[4][4];
                #pragma unroll
                for (int np = 0; np < 4; ++np)
                    ldsm4(b[np], bBufBase + (uint32_t)(np * 4096) + bCh);
                #pragma unroll
                for (int mi = 0; mi < 4; ++mi)
                    #pragma unroll
                    for (int np = 0; np < 4; ++np) {
                        mma16816h(acc[mi][np * 2 + 0], a[mi], b[np][0], b[np][1]);
                        mma16816h(acc[mi][np * 2 + 1], a[mi], b[np][2], b[np][3]);
                    }
            }

            // diagonal mask: global col tile ct = ct0+k hits diag when dt in 0..3
            {
                const int dt = (ct0 + k) - 4 * rt;
                if (dt >= 0 && dt <= 3) {
                    const int coff = dt * 128;
                    #pragma unroll
                    for (int mi = 0; mi < 4; ++mi) {
                        int r0 = wm * 64 + mi * 16 + (lane >> 2);
                        #pragma unroll
                        for (int ni = 0; ni < 8; ++ni) {
                            int c0 = wn * 64 + ni * 8 + (lane & 3) * 2 + coff;
                            if (c0     == r0)     acc[mi][ni][0] = (acc[mi][ni][0] & 0xFFFF0000u) | NEGINF_LO;
                            if (c0 + 1 == r0)     acc[mi][ni][0] = (acc[mi][ni][0] & 0x0000FFFFu) | NEGINF_HI;
                            if (c0     == r0 + 8) acc[mi][ni][1] = (acc[mi][ni][1] & 0xFFFF0000u) | NEGINF_LO;
                            if (c0 + 1 == r0 + 8) acc[mi][ni][1] = (acc[mi][ni][1] & 0x0000FFFFu) | NEGINF_HI;
                        }
                    }
                }
            }
            #pragma unroll
            for (int mi = 0; mi < 4; ++mi)
                #pragma unroll
                for (int ni = 0; ni < 8; ++ni) {
                    rmax2[mi][0] = hmax2(rmax2[mi][0], acc[mi][ni][0]);
                    rmax2[mi][1] = hmax2(rmax2[mi][1], acc[mi][ni][1]);
                }
        }

        // segment epilogue: collapse + quad reduce + atomicMax (exact)
        {
            float rmax[8];
            #pragma unroll
            for (int mi = 0; mi < 4; ++mi)
                #pragma unroll
                for (int rr = 0; rr < 2; ++rr) {
                    __half2 h = *(__half2*)&rmax2[mi][rr];
                    rmax[mi * 2 + rr] = fmaxf(__low2float(h), __high2float(h));
                }
            #pragma unroll
            for (int i = 0; i < 8; ++i) {
                rmax[i] = fmaxf(rmax[i], __shfl_xor_sync(0xFFFFFFFFu, rmax[i], 1));
                rmax[i] = fmaxf(rmax[i], __shfl_xor_sync(0xFFFFFFFFu, rmax[i], 2));
            }
            if ((lane & 3) == 0) {
                #pragma unroll
                for (int mi = 0; mi < 4; ++mi) {
                    int rA = rowBase + wm * 64 + mi * 16 + (lane >> 2);
                    atomicMax(&g_rowmax_enc[rA],     enc_f(rmax[mi * 2 + 0]));
                    atomicMax(&g_rowmax_enc[rA + 8], enc_f(rmax[mi * 2 + 1]));
                }
            }
        }

        i0 = i1;
    }

    // ---------------- grid barrier 2 ----------------------------------------
    __threadfence();
    __syncthreads();
    if (tid == 0) { atomicAdd(&g_done, 1); spin_until(&g_done, GRID_PERS); }
    __syncthreads();
    __threadfence();

    // ---------------- Phase 2a: per-CTA deterministic partial sum -----------
    {
        float* sum = (float*)smem;
        const int r0 = blockIdx.x * ROWS_PER_CTA;
        const int r1 = (r0 + ROWS_PER_CTA < BSZ) ? (r0 + ROWS_PER_CTA) : BSZ;
        float s = 0.0f;
        for (int b = r0 + tid; b < r1; b += 512)
            s += g_term1[b] + softplusf(dec_f(g_rowmax_enc[b]) - g_pos[b]);
        sum[tid] = s;
        __syncthreads();
        #pragma unroll
        for (int off = 256; off > 0; off >>= 1) {
            if (tid < off) sum[tid] += sum[tid + off];
            __syncthreads();
        }
        if (tid == 0) { g_part[blockIdx.x] = sum[0]; __threadfence(); }
    }

    // ---------------- Phase 2b: last CTA combines ---------------------------
    __syncthreads();
    if (tid == 0) s_flag = (atomicAdd(&g_done2, 1) == GRID_PERS - 1) ? 1 : 0;
    __syncthreads();
    if (s_flag) {
        __threadfence();
        float* sum = (float*)smem;
        sum[tid] = (tid < GRID_PERS) ? g_part[tid] : 0.0f;
        __syncthreads();
        #pragma unroll
        for (int off = 256; off > 0; off >>= 1) {
            if (tid < off) sum[tid] += sum[tid + off];
            __syncthreads();
        }
        if (tid == 0) {
            out[0] = sum[0] / (2.0f * (float)BSZ);
            g_prep = 0; g_done = 0; g_done2 = 0;
            __threadfence();
        }
    }
}

// ---------------------------------------------------------------------------
extern "C" void kernel_launch(void* const* d_in, const int* in_sizes, int n_in,
                              void* d_out, int out_size) {
    const float* q  = (const float*)d_in[0];
    const float* dd = (const float*)d_in[1];
    const float* nd = (const float*)d_in[2];
    float* out = (float*)d_out;

    cudaFuncSetAttribute(mega_kernel, cudaFuncAttributeMaxDynamicSharedMemorySize, SMEM_TOTAL);
    mega_kernel<<<GRID_PERS, 512, SMEM_TOTAL>>>(q, dd, nd, out);
}

// round 15
// speedup vs baseline: 1.5403x; 1.5403x over previous
#include <cuda_runtime.h>
#include <cuda_fp16.h>
#include <cstdint>

// ---------------------------------------------------------------------------
// Problem shape / tiling
// ---------------------------------------------------------------------------
#define BSZ    16384
#define DDIM   128
#define TILE_M 512               // rows per row-tile
#define TILE_N 128               // cols per tile step
#define NRT    (BSZ / TILE_M)    // 32 row tiles
#define NCHUNK 32                // items per row tile (4 col tiles each)
#define NITEMS (NRT * NCHUNK)    // 1024 work items
#define GRID_PERS 148
#define NWARPS_G (GRID_PERS * 16)
#define ROWS_PER_CTA 111
#define NEGINF_LO 0x0000FC00u
#define NEGINF_HI 0xFC000000u

// Scratch (device globals; allocation-free rule)
__device__ __align__(128) __half g_Qh[BSZ * DDIM];   // 4 MB
__device__ __align__(128) __half g_Dh[BSZ * DDIM];   // 4 MB
__device__ float    g_pos[BSZ];
__device__ float    g_term1[BSZ];
__device__ unsigned g_rowmax_enc[BSZ];
__device__ float    g_part[160];
__device__ int      g_prep;
__device__ int      g_done;
__device__ int      g_done2;

// ---------------------------------------------------------------------------
// helpers
// ---------------------------------------------------------------------------
__device__ __forceinline__ uint32_t smem_to_u32(const void* p) {
    uint32_t a;
    asm("{ .reg .u64 t; cvta.to.shared.u64 t, %1; cvt.u32.u64 %0, t; }" : "=r"(a) : "l"(p));
    return a;
}
__device__ __forceinline__ void cpasync16(uint32_t s, const void* g) {
    asm volatile("cp.async.cg.shared.global [%0], [%1], 16;" :: "r"(s), "l"(g));
}
#define CP_COMMIT() asm volatile("cp.async.commit_group;" ::: "memory")
#define CP_WAIT0()  asm volatile("cp.async.wait_group 0;" ::: "memory")
#define CP_WAIT1()  asm volatile("cp.async.wait_group 1;" ::: "memory")

__device__ __forceinline__ void ldsm4(uint32_t* r, uint32_t addr) {
    asm volatile("ldmatrix.sync.aligned.m8n8.x4.shared.b16 {%0,%1,%2,%3}, [%4];"
                 : "=r"(r[0]), "=r"(r[1]), "=r"(r[2]), "=r"(r[3]) : "r"(addr));
}
__device__ __forceinline__ void mma16816h(uint32_t* c, const uint32_t* a, uint32_t b0, uint32_t b1) {
    asm volatile("mma.sync.aligned.m16n8k16.row.col.f16.f16.f16.f16 "
                 "{%0,%1}, {%2,%3,%4,%5}, {%6,%7}, {%0,%1};"
                 : "+r"(c[0]), "+r"(c[1])
                 : "r"(a[0]), "r"(a[1]), "r"(a[2]), "r"(a[3]), "r"(b0), "r"(b1));
}
__device__ __forceinline__ uint32_t hmax2(uint32_t a, uint32_t b) {
    uint32_t d;
    asm("max.f16x2 %0, %1, %2;" : "=r"(d) : "r"(a), "r"(b));
    return d;
}
__device__ __forceinline__ float softplusf(float x) {
    return x > 20.0f ? x : log1pf(__expf(x));
}
__device__ __forceinline__ unsigned enc_f(float x) {
    unsigned u = __float_as_uint(x);
    return (u & 0x80000000u) ? ~u : (u | 0x80000000u);
}
__device__ __forceinline__ float dec_f(unsigned e) {
    unsigned u = (e & 0x80000000u) ? (e & 0x7FFFFFFFu) : ~e;
    return __uint_as_float(u);
}
__device__ __forceinline__ void spin_until(int* ctr, int target) {
    while (atomicAdd(ctr, 0) < target) { __nanosleep(64); }
}

// ---------------------------------------------------------------------------
// smem: A (512 rows x 256B = 128KB) + B ring x3 (128 rows x 256B each)
// ---------------------------------------------------------------------------
#define SMEM_A     0
#define SMEM_BR    131072          // + slot * 32768, 3 slots
#define SMEM_TOTAL 229376

// swizzle: 16B chunk c of row r lives at chunk (c ^ (r & 7))
__device__ __forceinline__ void load_tileA_sw(uint32_t dst, const __half* src,
                                              int rowBase, int tid) {
    const char* s = (const char*)(src + (size_t)rowBase * DDIM);
    #pragma unroll
    for (int i = 0; i < 16; ++i) {
        int e = tid + 512 * i;         // 8192 chunks (512 rows x 16)
        int r = e >> 4;
        int c = e & 15;
        cpasync16(dst + r * 256 + ((c ^ (r & 7)) << 4), s + (size_t)r * 256 + c * 16);
    }
}
__device__ __forceinline__ void load_tileB_sw(uint32_t dst, const __half* src,
                                              int rowBase, int tid) {
    const char* s = (const char*)(src + (size_t)rowBase * DDIM);
    #pragma unroll
    for (int i = 0; i < 4; ++i) {
        int e = tid + 512 * i;         // 2048 chunks (128 rows x 16)
        int r = e >> 4;
        int c = e & 15;
        cpasync16(dst + r * 256 + ((c ^ (r & 7)) << 4), s + (size_t)r * 256 + c * 16);
    }
}

// ---------------------------------------------------------------------------
// ONE persistent kernel; static contiguous item partition, A reused per segment
// ---------------------------------------------------------------------------
__global__ void __launch_bounds__(512, 1)
mega_kernel(const float* __restrict__ q, const float* __restrict__ d,
            const float* __restrict__ nd, float* __restrict__ out) {
    extern __shared__ __align__(1024) char smem[];
    __shared__ int s_flag;
    const uint32_t sb = smem_to_u32(smem);
    const int tid  = threadIdx.x;
    const int lane = tid & 31;
    const int wid  = tid >> 5;
    const int wm   = wid >> 1;        // 0..7  (M position, 64 rows each)
    const int wn   = wid & 1;         // 0..1  (N position, 64 cols each)

    // ---------------- Phase 0: prep ----------------------------------------
    {
        int gw = blockIdx.x * 16 + wid;
        for (int row = gw; row < BSZ; row += NWARPS_G) {
            const float4 qv = *(const float4*)(q  + (size_t)row * DDIM + lane * 4);
            const float4 dv = *(const float4*)(d  + (size_t)row * DDIM + lane * 4);
            const float4 nv = *(const float4*)(nd + (size_t)row * DDIM + lane * 4);

            __half2* qdst = (__half2*)(g_Qh + (size_t)row * DDIM + lane * 4);
            qdst[0] = __floats2half2_rn(qv.x, qv.y);
            qdst[1] = __floats2half2_rn(qv.z, qv.w);
            __half2* ddst = (__half2*)(g_Dh + (size_t)row * DDIM + lane * 4);
            ddst[0] = __floats2half2_rn(dv.x, dv.y);
            ddst[1] = __floats2half2_rn(dv.z, dv.w);

            float pos = qv.x * dv.x + qv.y * dv.y + qv.z * dv.z + qv.w * dv.w;
            float neg = qv.x * nv.x + qv.y * nv.y + qv.z * nv.z + qv.w * nv.w;
            #pragma unroll
            for (int off = 16; off > 0; off >>= 1) {
                pos += __shfl_xor_sync(0xFFFFFFFFu, pos, off);
                neg += __shfl_xor_sync(0xFFFFFFFFu, neg, off);
            }
            if (lane == 0) {
                g_pos[row]   = pos;
                g_term1[row] = softplusf(neg - pos);
                g_rowmax_enc[row] = 0u;
            }
        }
    }
    __threadfence();
    __syncthreads();
    if (tid == 0) { atomicAdd(&g_prep, 1); spin_until(&g_prep, GRID_PERS); }
    __syncthreads();

    // ---------------- Phase 1: static-partition max-GEMM --------------------
    const int xr  = lane & 7;
    const int hcA = (lane >> 4) & 1;
    const int hcB = (lane >> 3) & 1;
    const uint32_t aRow    = (uint32_t)((wm * 64 + (lane & 15)) * 256);
    const uint32_t bRowOff = (uint32_t)((wn * 64 + ((lane >> 4) << 3) + (lane & 7)) * 256);

    const int iStart = (blockIdx.x * NITEMS) / GRID_PERS;
    const int iEnd   = ((blockIdx.x + 1) * NITEMS) / GRID_PERS;

    int i0 = iStart;
    while (i0 < iEnd) {
        const int rt = i0 >> 5;                         // row tile of this segment
        const int i1 = min(iEnd, (rt + 1) << 5);        // segment end (same rt)
        const int rowBase = rt * TILE_M;
        const int ct0 = (i0 & 31) * 4;                  // first global col tile
        const int ctN = (i1 - i0) * 4;                  // number of col tiles

        __syncthreads();   // all warps past previous segment's smem reads

        // prologue: group0 = A + B(ct0); group1 = B(ct0+1) (maybe empty)
        load_tileA_sw(sb + SMEM_A, g_Qh, rowBase, tid);
        load_tileB_sw(sb + SMEM_BR, g_Dh, (ct0 + 0) * TILE_N, tid);
        CP_COMMIT();
        if (ctN > 1)
            load_tileB_sw(sb + SMEM_BR + 32768, g_Dh, (ct0 + 1) * TILE_N, tid);
        CP_COMMIT();

        uint32_t rmax2[4][2];
        #pragma unroll
        for (int mi = 0; mi < 4; ++mi) { rmax2[mi][0] = 0xFC00FC00u; rmax2[mi][1] = 0xFC00FC00u; }

        for (int k = 0; k < ctN; ++k) {
            CP_WAIT1();            // group k complete
            __syncthreads();
            // prefetch B(ct0+k+2); ALWAYS commit to keep group count uniform
            if (k + 2 < ctN)
                load_tileB_sw(sb + SMEM_BR + (uint32_t)(((k + 2) % 3) * 32768),
                              g_Dh, (ct0 + k + 2) * TILE_N, tid);
            CP_COMMIT();

            const uint32_t aBufBase = sb + SMEM_A + aRow;
            const uint32_t bBufBase = sb + SMEM_BR + (uint32_t)((k % 3) * 32768) + bRowOff;

            uint32_t acc[4][8][2];
            #pragma unroll
            for (int mi = 0; mi < 4; ++mi)
                #pragma unroll
                for (int ni = 0; ni < 8; ++ni) { acc[mi][ni][0] = 0u; acc[mi][ni][1] = 0u; }

            #pragma unroll
            for (int ks = 0; ks < 8; ++ks) {
                const uint32_t aCh = (uint32_t)(((ks * 2 + hcA) ^ xr) << 4);
                const uint32_t bCh = (uint32_t)(((ks * 2 + hcB) ^ xr) << 4);
                uint32_t a[4][4];
                #pragma unroll
                for (int mi = 0; mi < 4; ++mi)
                    ldsm4(a[mi], aBufBase + (uint32_t)(mi * 4096) + aCh);
                uint32_t b[4][4];
                #pragma unroll
                for (int np = 0; np < 4; ++np)
                    ldsm4(b[np], bBufBase + (uint32_t)(np * 4096) + bCh);
                #pragma unroll
                for (int mi = 0; mi < 4; ++mi)
                    #pragma unroll
                    for (int np = 0; np < 4; ++np) {
                        mma16816h(acc[mi][np * 2 + 0], a[mi], b[np][0], b[np][1]);
                        mma16816h(acc[mi][np * 2 + 1], a[mi], b[np][2], b[np][3]);
                    }
            }

            // diagonal mask: global col tile ct = ct0+k hits diag when dt in 0..3
            {
                const int dt = (ct0 + k) - 4 * rt;
                if (dt >= 0 && dt <= 3) {
                    const int coff = dt * 128;
                    #pragma unroll
                    for (int mi = 0; mi < 4; ++mi) {
                        int r0 = wm * 64 + mi * 16 + (lane >> 2);
                        #pragma unroll
                        for (int ni = 0; ni < 8; ++ni) {
                            int c0 = wn * 64 + ni * 8 + (lane & 3) * 2 + coff;
                            if (c0     == r0)     acc[mi][ni][0] = (acc[mi][ni][0] & 0xFFFF0000u) | NEGINF_LO;
                            if (c0 + 1 == r0)     acc[mi][ni][0] = (acc[mi][ni][0] & 0x0000FFFFu) | NEGINF_HI;
                            if (c0     == r0 + 8) acc[mi][ni][1] = (acc[mi][ni][1] & 0xFFFF0000u) | NEGINF_LO;
                            if (c0 + 1 == r0 + 8) acc[mi][ni][1] = (acc[mi][ni][1] & 0x0000FFFFu) | NEGINF_HI;
                        }
                    }
                }
            }
            #pragma unroll
            for (int mi = 0; mi < 4; ++mi)
                #pragma unroll
                for (int ni = 0; ni < 8; ++ni) {
                    rmax2[mi][0] = hmax2(rmax2[mi][0], acc[mi][ni][0]);
                    rmax2[mi][1] = hmax2(rmax2[mi][1], acc[mi][ni][1]);
                }
        }

        // segment epilogue: collapse + quad reduce + atomicMax (exact)
        {
            float rmax[8];
            #pragma unroll
            for (int mi = 0; mi < 4; ++mi)
                #pragma unroll
                for (int rr = 0; rr < 2; ++rr) {
                    __half2 h = *(__half2*)&rmax2[mi][rr];
                    rmax[mi * 2 + rr] = fmaxf(__low2float(h), __high2float(h));
                }
            #pragma unroll
            for (int i = 0; i < 8; ++i) {
                rmax[i] = fmaxf(rmax[i], __shfl_xor_sync(0xFFFFFFFFu, rmax[i], 1));
                rmax[i] = fmaxf(rmax[i], __shfl_xor_sync(0xFFFFFFFFu, rmax[i], 2));
            }
            if ((lane & 3) == 0) {
                #pragma unroll
                for (int mi = 0; mi < 4; ++mi) {
                    int rA = rowBase + wm * 64 + mi * 16 + (lane >> 2);
                    atomicMax(&g_rowmax_enc[rA],     enc_f(rmax[mi * 2 + 0]));
                    atomicMax(&g_rowmax_enc[rA + 8], enc_f(rmax[mi * 2 + 1]));
                }
            }
        }

        i0 = i1;
    }

    // ---------------- grid barrier 2 ----------------------------------------
    __threadfence();
    __syncthreads();
    if (tid == 0) { atomicAdd(&g_done, 1); spin_until(&g_done, GRID_PERS); }
    __syncthreads();
    __threadfence();

    // ---------------- Phase 2a: per-CTA deterministic partial sum -----------
    {
        float* sum = (float*)smem;
        const int r0 = blockIdx.x * ROWS_PER_CTA;
        const int r1 = (r0 + ROWS_PER_CTA < BSZ) ? (r0 + ROWS_PER_CTA) : BSZ;
        float s = 0.0f;
        for (int b = r0 + tid; b < r1; b += 512)
            s += g_term1[b] + softplusf(dec_f(g_rowmax_enc[b]) - g_pos[b]);
        sum[tid] = s;
        __syncthreads();
        #pragma unroll
        for (int off = 256; off > 0; off >>= 1) {
            if (tid < off) sum[tid] += sum[tid + off];
            __syncthreads();
        }
        if (tid == 0) { g_part[blockIdx.x] = sum[0]; __threadfence(); }
    }

    // ---------------- Phase 2b: last CTA combines ---------------------------
    __syncthreads();
    if (tid == 0) s_flag = (atomicAdd(&g_done2, 1) == GRID_PERS - 1) ? 1 : 0;
    __syncthreads();
    if (s_flag) {
        __threadfence();
        float* sum = (float*)smem;
        sum[tid] = (tid < GRID_PERS) ? g_part[tid] : 0.0f;
        __syncthreads();
        #pragma unroll
        for (int off = 256; off > 0; off >>= 1) {
            if (tid < off) sum[tid] += sum[tid + off];
            __syncthreads();
        }
        if (tid == 0) {
            out[0] = sum[0] / (2.0f * (float)BSZ);
            g_prep = 0; g_done = 0; g_done2 = 0;
            __threadfence();
        }
    }
}

// ---------------------------------------------------------------------------
extern "C" void kernel_launch(void* const* d_in, const int* in_sizes, int n_in,
                              void* d_out, int out_size) {
    const float* q  = (const float*)d_in[0];
    const float* dd = (const float*)d_in[1];
    const float* nd = (const float*)d_in[2];
    float* out = (float*)d_out;

    cudaFuncSetAttribute(mega_kernel, cudaFuncAttributeMaxDynamicSharedMemorySize, SMEM_TOTAL);
    mega_kernel<<<GRID_PERS, 512, SMEM_TOTAL>>>(q, dd, nd, out);
}

// round 16
// speedup vs baseline: 1.5492x; 1.0058x over previous
#include <cuda_runtime.h>
#include <cuda_fp16.h>
#include <cstdint>

// ---------------------------------------------------------------------------
// Problem shape / tiling
// ---------------------------------------------------------------------------
#define BSZ    16384
#define DDIM   128
#define TILE_M 512               // rows per row-tile
#define TILE_N 128               // cols per tile step
#define NRT    (BSZ / TILE_M)    // 32 row tiles
#define NCHUNK 32                // items per row tile (4 col tiles each)
#define NITEMS (NRT * NCHUNK)    // 1024 work items
#define GRID_PERS 148
#define ROWS_PER_CTA 111
#define NEGINF_LO 0x0000FC00u
#define NEGINF_HI 0xFC000000u

// Scratch (device globals; allocation-free rule)
__device__ __align__(128) __half g_Qh[BSZ * DDIM];   // 4 MB
__device__ __align__(128) __half g_Dh[BSZ * DDIM];   // 4 MB
__device__ float    g_pos[BSZ];
__device__ float    g_term1[BSZ];
__device__ unsigned g_rowmax_enc[BSZ];
__device__ float    g_part[160];
__device__ int      g_done;
__device__ int      g_done2;

// ---------------------------------------------------------------------------
// helpers
// ---------------------------------------------------------------------------
__device__ __forceinline__ uint32_t smem_to_u32(const void* p) {
    uint32_t a;
    asm("{ .reg .u64 t; cvta.to.shared.u64 t, %1; cvt.u32.u64 %0, t; }" : "=r"(a) : "l"(p));
    return a;
}
__device__ __forceinline__ void cpasync16(uint32_t s, const void* g) {
    asm volatile("cp.async.cg.shared.global [%0], [%1], 16;" :: "r"(s), "l"(g));
}
#define CP_COMMIT() asm volatile("cp.async.commit_group;" ::: "memory")
#define CP_WAIT0()  asm volatile("cp.async.wait_group 0;" ::: "memory")
#define CP_WAIT1()  asm volatile("cp.async.wait_group 1;" ::: "memory")

__device__ __forceinline__ void ldsm4(uint32_t* r, uint32_t addr) {
    asm volatile("ldmatrix.sync.aligned.m8n8.x4.shared.b16 {%0,%1,%2,%3}, [%4];"
                 : "=r"(r[0]), "=r"(r[1]), "=r"(r[2]), "=r"(r[3]) : "r"(addr));
}
__device__ __forceinline__ void mma16816h(uint32_t* c, const uint32_t* a, uint32_t b0, uint32_t b1) {
    asm volatile("mma.sync.aligned.m16n8k16.row.col.f16.f16.f16.f16 "
                 "{%0,%1}, {%2,%3,%4,%5}, {%6,%7}, {%0,%1};"
                 : "+r"(c[0]), "+r"(c[1])
                 : "r"(a[0]), "r"(a[1]), "r"(a[2]), "r"(a[3]), "r"(b0), "r"(b1));
}
__device__ __forceinline__ uint32_t hmax2(uint32_t a, uint32_t b) {
    uint32_t d;
    asm("max.f16x2 %0, %1, %2;" : "=r"(d) : "r"(a), "r"(b));
    return d;
}
__device__ __forceinline__ float softplusf(float x) {
    return x > 20.0f ? x : log1pf(__expf(x));
}
__device__ __forceinline__ unsigned enc_f(float x) {
    unsigned u = __float_as_uint(x);
    return (u & 0x80000000u) ? ~u : (u | 0x80000000u);
}
__device__ __forceinline__ float dec_f(unsigned e) {
    unsigned u = (e & 0x80000000u) ? (e & 0x7FFFFFFFu) : ~e;
    return __uint_as_float(u);
}
__device__ __forceinline__ void spin_until(int* ctr, int target) {
    while (atomicAdd(ctr, 0) < target) { __nanosleep(64); }
}

// ---------------------------------------------------------------------------
// Kernel 1: prep (own register allocation -> safe 2-row unroll, MLP=6)
// One warp handles rows gw and gw + BSZ/2.
// ---------------------------------------------------------------------------
__device__ __forceinline__ void prep_row(int row, int lane,
                                         const float4& qv, const float4& dv, const float4& nv) {
    __half2* qdst = (__half2*)(g_Qh + (size_t)row * DDIM + lane * 4);
    qdst[0] = __floats2half2_rn(qv.x, qv.y);
    qdst[1] = __floats2half2_rn(qv.z, qv.w);
    __half2* ddst = (__half2*)(g_Dh + (size_t)row * DDIM + lane * 4);
    ddst[0] = __floats2half2_rn(dv.x, dv.y);
    ddst[1] = __floats2half2_rn(dv.z, dv.w);

    float pos = qv.x * dv.x + qv.y * dv.y + qv.z * dv.z + qv.w * dv.w;
    float neg = qv.x * nv.x + qv.y * nv.y + qv.z * nv.z + qv.w * nv.w;
    #pragma unroll
    for (int off = 16; off > 0; off >>= 1) {
        pos += __shfl_xor_sync(0xFFFFFFFFu, pos, off);
        neg += __shfl_xor_sync(0xFFFFFFFFu, neg, off);
    }
    if (lane == 0) {
        g_pos[row]   = pos;
        g_term1[row] = softplusf(neg - pos);
        g_rowmax_enc[row] = 0u;
    }
}

__global__ void __launch_bounds__(256)
prep_kernel(const float* __restrict__ q, const float* __restrict__ d,
            const float* __restrict__ nd) {
    const int lane = threadIdx.x & 31;
    const int row1 = blockIdx.x * 8 + (threadIdx.x >> 5);   // 0..8191
    const int row2 = row1 + BSZ / 2;

    const float4 qv1 = *(const float4*)(q  + (size_t)row1 * DDIM + lane * 4);
    const float4 dv1 = *(const float4*)(d  + (size_t)row1 * DDIM + lane * 4);
    const float4 nv1 = *(const float4*)(nd + (size_t)row1 * DDIM + lane * 4);
    const float4 qv2 = *(const float4*)(q  + (size_t)row2 * DDIM + lane * 4);
    const float4 dv2 = *(const float4*)(d  + (size_t)row2 * DDIM + lane * 4);
    const float4 nv2 = *(const float4*)(nd + (size_t)row2 * DDIM + lane * 4);

    prep_row(row1, lane, qv1, dv1, nv1);
    prep_row(row2, lane, qv2, dv2, nv2);
}

// ---------------------------------------------------------------------------
// smem: A (512 rows x 256B = 128KB) + B ring x3 (128 rows x 256B each)
// ---------------------------------------------------------------------------
#define SMEM_A     0
#define SMEM_BR    131072          // + slot * 32768, 3 slots
#define SMEM_TOTAL 229376

// swizzle: 16B chunk c of row r lives at chunk (c ^ (r & 7))
__device__ __forceinline__ void load_tileA_sw(uint32_t dst, const __half* src,
                                              int rowBase, int tid) {
    const char* s = (const char*)(src + (size_t)rowBase * DDIM);
    #pragma unroll
    for (int i = 0; i < 16; ++i) {
        int e = tid + 512 * i;         // 8192 chunks (512 rows x 16)
        int r = e >> 4;
        int c = e & 15;
        cpasync16(dst + r * 256 + ((c ^ (r & 7)) << 4), s + (size_t)r * 256 + c * 16);
    }
}
__device__ __forceinline__ void load_tileB_sw(uint32_t dst, const __half* src,
                                              int rowBase, int tid) {
    const char* s = (const char*)(src + (size_t)rowBase * DDIM);
    #pragma unroll
    for (int i = 0; i < 4; ++i) {
        int e = tid + 512 * i;         // 2048 chunks (128 rows x 16)
        int r = e >> 4;
        int c = e & 15;
        cpasync16(dst + r * 256 + ((c ^ (r & 7)) << 4), s + (size_t)r * 256 + c * 16);
    }
}

// ---------------------------------------------------------------------------
// Kernel 2: persistent max-GEMM + finalize (R12 phases 1-2, verbatim)
// ---------------------------------------------------------------------------
__global__ void __launch_bounds__(512, 1)
mega_kernel(float* __restrict__ out) {
    extern __shared__ __align__(1024) char smem[];
    __shared__ int s_flag;
    const uint32_t sb = smem_to_u32(smem);
    const int tid  = threadIdx.x;
    const int lane = tid & 31;
    const int wid  = tid >> 5;
    const int wm   = wid >> 1;        // 0..7  (M position, 64 rows each)
    const int wn   = wid & 1;         // 0..1  (N position, 64 cols each)

    // ---------------- Phase 1: static-partition max-GEMM --------------------
    const int xr  = lane & 7;
    const int hcA = (lane >> 4) & 1;
    const int hcB = (lane >> 3) & 1;
    const uint32_t aRow    = (uint32_t)((wm * 64 + (lane & 15)) * 256);
    const uint32_t bRowOff = (uint32_t)((wn * 64 + ((lane >> 4) << 3) + (lane & 7)) * 256);

    const int iStart = (blockIdx.x * NITEMS) / GRID_PERS;
    const int iEnd   = ((blockIdx.x + 1) * NITEMS) / GRID_PERS;

    int i0 = iStart;
    while (i0 < iEnd) {
        const int rt = i0 >> 5;                         // row tile of this segment
        const int i1 = min(iEnd, (rt + 1) << 5);        // segment end (same rt)
        const int rowBase = rt * TILE_M;
        const int ct0 = (i0 & 31) * 4;                  // first global col tile
        const int ctN = (i1 - i0) * 4;                  // number of col tiles

        __syncthreads();   // all warps past previous segment's smem reads

        // prologue: group0 = A + B(ct0); group1 = B(ct0+1) (maybe empty)
        load_tileA_sw(sb + SMEM_A, g_Qh, rowBase, tid);
        load_tileB_sw(sb + SMEM_BR, g_Dh, (ct0 + 0) * TILE_N, tid);
        CP_COMMIT();
        if (ctN > 1)
            load_tileB_sw(sb + SMEM_BR + 32768, g_Dh, (ct0 + 1) * TILE_N, tid);
        CP_COMMIT();

        uint32_t rmax2[4][2];
        #pragma unroll
        for (int mi = 0; mi < 4; ++mi) { rmax2[mi][0] = 0xFC00FC00u; rmax2[mi][1] = 0xFC00FC00u; }

        for (int k = 0; k < ctN; ++k) {
            CP_WAIT1();            // group k complete
            __syncthreads();
            // prefetch B(ct0+k+2); ALWAYS commit to keep group count uniform
            if (k + 2 < ctN)
                load_tileB_sw(sb + SMEM_BR + (uint32_t)(((k + 2) % 3) * 32768),
                              g_Dh, (ct0 + k + 2) * TILE_N, tid);
            CP_COMMIT();

            const uint32_t aBufBase = sb + SMEM_A + aRow;
            const uint32_t bBufBase = sb + SMEM_BR + (uint32_t)((k % 3) * 32768) + bRowOff;

            uint32_t acc[4][8][2];
            #pragma unroll
            for (int mi = 0; mi < 4; ++mi)
                #pragma unroll
                for (int ni = 0; ni < 8; ++ni) { acc[mi][ni][0] = 0u; acc[mi][ni][1] = 0u; }

            #pragma unroll
            for (int ks = 0; ks < 8; ++ks) {
                const uint32_t aCh = (uint32_t)(((ks * 2 + hcA) ^ xr) << 4);
                const uint32_t bCh = (uint32_t)(((ks * 2 + hcB) ^ xr) << 4);
                uint32_t a[4][4];
                #pragma unroll
                for (int mi = 0; mi < 4; ++mi)
                    ldsm4(a[mi], aBufBase + (uint32_t)(mi * 4096) + aCh);
                uint32_t b[4][4];
                #pragma unroll
                for (int np = 0; np < 4; ++np)
                    ldsm4(b[np], bBufBase + (uint32_t)(np * 4096) + bCh);
                #pragma unroll
                for (int mi = 0; mi < 4; ++mi)
                    #pragma unroll
                    for (int np = 0; np < 4; ++np) {
                        mma16816h(acc[mi][np * 2 + 0], a[mi], b[np][0], b[np][1]);
                        mma16816h(acc[mi][np * 2 + 1], a[mi], b[np][2], b[np][3]);
                    }
            }

            // diagonal mask: global col tile ct = ct0+k hits diag when dt in 0..3
            {
                const int dt = (ct0 + k) - 4 * rt;
                if (dt >= 0 && dt <= 3) {
                    const int coff = dt * 128;
                    #pragma unroll
                    for (int mi = 0; mi < 4; ++mi) {
                        int r0 = wm * 64 + mi * 16 + (lane >> 2);
                        #pragma unroll
                        for (int ni = 0; ni < 8; ++ni) {
                            int c0 = wn * 64 + ni * 8 + (lane & 3) * 2 + coff;
                            if (c0     == r0)     acc[mi][ni][0] = (acc[mi][ni][0] & 0xFFFF0000u) | NEGINF_LO;
                            if (c0 + 1 == r0)     acc[mi][ni][0] = (acc[mi][ni][0] & 0x0000FFFFu) | NEGINF_HI;
                            if (c0     == r0 + 8) acc[mi][ni][1] = (acc[mi][ni][1] & 0xFFFF0000u) | NEGINF_LO;
                            if (c0 + 1 == r0 + 8) acc[mi][ni][1] = (acc[mi][ni][1] & 0x0000FFFFu) | NEGINF_HI;
                        }
                    }
                }
            }
            #pragma unroll
            for (int mi = 0; mi < 4; ++mi)
                #pragma unroll
                for (int ni = 0; ni < 8; ++ni) {
                    rmax2[mi][0] = hmax2(rmax2[mi][0], acc[mi][ni][0]);
                    rmax2[mi][1] = hmax2(rmax2[mi][1], acc[mi][ni][1]);
                }
        }

        // segment epilogue: collapse + quad reduce + atomicMax (exact)
        {
            float rmax[8];
            #pragma unroll
            for (int mi = 0; mi < 4; ++mi)
                #pragma unroll
                for (int rr = 0; rr < 2; ++rr) {
                    __half2 h = *(__half2*)&rmax2[mi][rr];
                    rmax[mi * 2 + rr] = fmaxf(__low2float(h), __high2float(h));
                }
            #pragma unroll
            for (int i = 0; i < 8; ++i) {
                rmax[i] = fmaxf(rmax[i], __shfl_xor_sync(0xFFFFFFFFu, rmax[i], 1));
                rmax[i] = fmaxf(rmax[i], __shfl_xor_sync(0xFFFFFFFFu, rmax[i], 2));
            }
            if ((lane & 3) == 0) {
                #pragma unroll
                for (int mi = 0; mi < 4; ++mi) {
                    int rA = rowBase + wm * 64 + mi * 16 + (lane >> 2);
                    atomicMax(&g_rowmax_enc[rA],     enc_f(rmax[mi * 2 + 0]));
                    atomicMax(&g_rowmax_enc[rA + 8], enc_f(rmax[mi * 2 + 1]));
                }
            }
        }

        i0 = i1;
    }

    // ---------------- grid barrier: all rowmax merges complete --------------
    __threadfence();
    __syncthreads();
    if (tid == 0) { atomicAdd(&g_done, 1); spin_until(&g_done, GRID_PERS); }
    __syncthreads();
    __threadfence();

    // ---------------- Phase 2a: per-CTA deterministic partial sum -----------
    {
        float* sum = (float*)smem;
        const int r0 = blockIdx.x * ROWS_PER_CTA;
        const int r1 = (r0 + ROWS_PER_CTA < BSZ) ? (r0 + ROWS_PER_CTA) : BSZ;
        float s = 0.0f;
        for (int b = r0 + tid; b < r1; b += 512)
            s += g_term1[b] + softplusf(dec_f(g_rowmax_enc[b]) - g_pos[b]);
        sum[tid] = s;
        __syncthreads();
        #pragma unroll
        for (int off = 256; off > 0; off >>= 1) {
            if (tid < off) sum[tid] += sum[tid + off];
            __syncthreads();
        }
        if (tid == 0) { g_part[blockIdx.x] = sum[0]; __threadfence(); }
    }

    // ---------------- Phase 2b: last CTA combines ---------------------------
    __syncthreads();
    if (tid == 0) s_flag = (atomicAdd(&g_done2, 1) == GRID_PERS - 1) ? 1 : 0;
    __syncthreads();
    if (s_flag) {
        __threadfence();
        float* sum = (float*)smem;
        sum[tid] = (tid < GRID_PERS) ? g_part[tid] : 0.0f;
        __syncthreads();
        #pragma unroll
        for (int off = 256; off > 0; off >>= 1) {
            if (tid < off) sum[tid] += sum[tid + off];
            __syncthreads();
        }
        if (tid == 0) {
            out[0] = sum[0] / (2.0f * (float)BSZ);
            g_done = 0; g_done2 = 0;
            __threadfence();
        }
    }
}

// ---------------------------------------------------------------------------
extern "C" void kernel_launch(void* const* d_in, const int* in_sizes, int n_in,
                              void* d_out, int out_size) {
    const float* q  = (const float*)d_in[0];
    const float* dd = (const float*)d_in[1];
    const float* nd = (const float*)d_in[2];
    float* out = (float*)d_out;

    cudaFuncSetAttribute(mega_kernel, cudaFuncAttributeMaxDynamicSharedMemorySize, SMEM_TOTAL);

    prep_kernel<<<BSZ / 16, 256>>>(q, dd, nd);    // 1024 blocks, 2 rows/warp
    mega_kernel<<<GRID_PERS, 512, SMEM_TOTAL>>>(out);
}